// round 3
// baseline (speedup 1.0000x reference)
#include <cuda_runtime.h>
#include <cstdint>

// Problem constants (fixed by the reference)
#define BATCH 4
#define DIM   192
#define RED   48          // DIM / 4
#define H     256
#define W     256
#define KK    9           // 3x3
#define EPS   1e-5f
#define NCH   (BATCH * DIM)   // 768 channel-slices
#define HW    (H * W)         // 65536 pixels per slice

// Scratch (allocation-free rule: __device__ globals)
__device__ float  g_pooled[NCH];      // per (b,c) mean
__device__ float4 g_wt4[NCH];         // masked taps: (w00, w01, w02, w10)

// ---------------------------------------------------------------------------
// Kernel 1: global average pool. One block per (b,c) slice; 256 threads
// each accumulate 64 float4's, then tree-reduce in shared.
// ---------------------------------------------------------------------------
__global__ void __launch_bounds__(256) pool_kernel(const float* __restrict__ x) {
    const int bc  = blockIdx.x;               // 0..767
    const int tid = threadIdx.x;
    const float4* xin = reinterpret_cast<const float4*>(x + (size_t)bc * HW);

    float acc = 0.f;
    #pragma unroll 8
    for (int i = tid; i < HW / 4; i += 256) {
        float4 v = __ldg(xin + i);
        acc += (v.x + v.y) + (v.z + v.w);
    }
    __shared__ float sred[256];
    sred[tid] = acc;
    __syncthreads();
    #pragma unroll
    for (int s = 128; s >= 32; s >>= 1) {
        if (tid < s) sred[tid] += sred[tid + s];
        __syncthreads();
    }
    if (tid < 32) {
        float v = sred[tid];
        #pragma unroll
        for (int off = 16; off; off >>= 1)
            v += __shfl_down_sync(0xffffffffu, v, off);
        if (tid == 0) g_pooled[bc] = v * (1.f / (float)HW);
    }
}

// ---------------------------------------------------------------------------
// Kernel 2: dynamic weight generation.
// One block per batch sample, 192 threads.
//   stage a: load pooled[b,:] into smem
//   stage b: threads 0..47 compute t[j] = relu(BN(pooled @ w1^T))
//   stage c: thread c computes the 4 surviving masked taps:
//            taps at flat k = 0,1,2 (ky=0) and k = 3 (ky=1,kx=0)
// ---------------------------------------------------------------------------
__global__ void __launch_bounds__(192) weights_kernel(
    const float* __restrict__ w1,            // [48,192]
    const float* __restrict__ gamma,
    const float* __restrict__ beta,
    const float* __restrict__ rmean,
    const float* __restrict__ rvar,
    const float* __restrict__ w2,            // [1728,48]
    const float* __restrict__ b2)            // [1728]
{
    const int b   = blockIdx.x;   // 0..3
    const int tid = threadIdx.x;  // 0..191

    __shared__ float sp[DIM];     // pooled[b,:]
    __shared__ float st[RED];     // t[b,:]

    sp[tid] = g_pooled[b * DIM + tid];
    __syncthreads();

    if (tid < RED) {
        const float* w1r = w1 + tid * DIM;
        float acc = 0.f;
        #pragma unroll 4
        for (int k = 0; k < DIM; k++) acc += sp[k] * __ldg(w1r + k);
        float v = __ldg(gamma + tid) * (acc - __ldg(rmean + tid))
                  * rsqrtf(__ldg(rvar + tid) + EPS) + __ldg(beta + tid);
        st[tid] = fmaxf(v, 0.f);
    }
    __syncthreads();

    // Each thread = one channel c; compute taps k=0..3 (the only unmasked ones)
    const int c = tid;
    float tap[4];
    #pragma unroll
    for (int k = 0; k < 4; k++) {
        const int row = c * KK + k;
        const float* w2r = w2 + row * RED;
        float acc = __ldg(b2 + row);
        #pragma unroll
        for (int j = 0; j < RED; j++) acc += st[j] * __ldg(w2r + j);
        tap[k] = acc;
    }
    g_wt4[b * DIM + c] = make_float4(tap[0], tap[1], tap[2], tap[3]);
}

// ---------------------------------------------------------------------------
// Kernel 3: masked depthwise conv (4 active taps) + bias.
// out[y][x] = w00*in[y-1][x-1] + w01*in[y-1][x] + w02*in[y-1][x+1]
//           + w10*in[y][x-1] + bias[c]
// Grid: (HW/4/256, NCH). Each thread produces one float4 of output.
// ---------------------------------------------------------------------------
__global__ void __launch_bounds__(256) conv_kernel(
    const float* __restrict__ x,
    const float* __restrict__ bias,
    float* __restrict__ out)
{
    const int bc = blockIdx.y;                      // 0..767
    const int c  = bc - (bc / DIM) * DIM;           // bc % DIM
    const float* xin = x   + (size_t)bc * HW;
    float*       o   = out + (size_t)bc * HW;

    const float4 wv = g_wt4[bc];                    // uniform per block
    const float  bv = __ldg(bias + c);

    const int fidx = blockIdx.x * 256 + threadIdx.x; // 0..16383
    const int pix  = fidx << 2;
    const int y    = pix >> 8;                       // row
    const int x0   = pix & 255;                      // col (multiple of 4)

    // row above (y-1): need cols x0-1 .. x0+4
    float4 up = make_float4(0.f, 0.f, 0.f, 0.f);
    float upL = 0.f, upR = 0.f;
    if (y > 0) {
        const float* ru = xin + (y - 1) * W + x0;
        up  = *reinterpret_cast<const float4*>(ru);
        if (x0 > 0)       upL = ru[-1];
        if (x0 + 4 < W)   upR = ru[4];
    }
    // center row (y): need cols x0-1 .. x0+2
    const float* rc = xin + y * W + x0;
    const float4 cu = *reinterpret_cast<const float4*>(rc);
    const float cuL = (x0 > 0) ? rc[-1] : 0.f;

    float4 r;
    r.x = fmaf(wv.x, upL,  fmaf(wv.y, up.x, fmaf(wv.z, up.y, fmaf(wv.w, cuL,  bv))));
    r.y = fmaf(wv.x, up.x, fmaf(wv.y, up.y, fmaf(wv.z, up.z, fmaf(wv.w, cu.x, bv))));
    r.z = fmaf(wv.x, up.y, fmaf(wv.y, up.z, fmaf(wv.z, up.w, fmaf(wv.w, cu.y, bv))));
    r.w = fmaf(wv.x, up.z, fmaf(wv.y, up.w, fmaf(wv.z, upR,  fmaf(wv.w, cu.z, bv))));

    *reinterpret_cast<float4*>(o + y * W + x0) = r;
}

// ---------------------------------------------------------------------------
// Launch. Inputs (metadata order):
// 0:x 1:w1 2:gamma 3:beta 4:running_mean 5:running_var 6:w2 7:b2 8:bias
// ---------------------------------------------------------------------------
extern "C" void kernel_launch(void* const* d_in, const int* in_sizes, int n_in,
                              void* d_out, int out_size) {
    const float* x     = (const float*)d_in[0];
    const float* w1    = (const float*)d_in[1];
    const float* gamma = (const float*)d_in[2];
    const float* beta  = (const float*)d_in[3];
    const float* rmean = (const float*)d_in[4];
    const float* rvar  = (const float*)d_in[5];
    const float* w2    = (const float*)d_in[6];
    const float* b2    = (const float*)d_in[7];
    const float* bias  = (const float*)d_in[8];
    float* out = (float*)d_out;

    pool_kernel<<<NCH, 256>>>(x);
    weights_kernel<<<BATCH, DIM>>>(w1, gamma, beta, rmean, rvar, w2, b2);
    conv_kernel<<<dim3(HW / 4 / 256, NCH), 256>>>(x, bias, out);
}